// round 2
// baseline (speedup 1.0000x reference)
#include <cuda_runtime.h>

#define N_NODES 1024
#define N_EDGES 32768
#define KE 32
#define KOUT 32
#define DIN 64
#define DOUT 64
#define DNODE 64
#define TMPW 160        // 32 SP + 32 (SPW2*SPW3) + 64 diag + 32 matmul
#define HID 256

// -------- device scratch (static; no runtime allocation) --------
__device__ float g_h[N_NODES * DNODE];
__device__ float g_X4[N_EDGES * KE];
__device__ float g_X5[N_EDGES * KE];
__device__ int   g_eid[N_NODES * N_NODES];
__device__ int   g_rowcnt[N_NODES];
__device__ int   g_fill[N_NODES];
__device__ int   g_rowptr[N_NODES + 1];
__device__ int   g_rowedges[N_EDGES];
__device__ float g_TMP[(size_t)N_EDGES * TMPW];
__device__ float g_H[(size_t)N_EDGES * HID];
__device__ float g_AGG[N_NODES * KOUT * DIN];

// ---------------------------------------------------------------
// K0: reset edge-id table and per-row counters (idempotent per call)
__global__ void k_init() {
    int idx = blockIdx.x * blockDim.x + threadIdx.x;
    int stride = gridDim.x * blockDim.x;
    for (int i = idx; i < N_NODES * N_NODES; i += stride) g_eid[i] = -1;
    if (idx < N_NODES) { g_rowcnt[idx] = 0; g_fill[idx] = 0; }
}

// K1: h = x @ Wnode^T   [N, 64]
__global__ void k_h(const float* __restrict__ x, const float* __restrict__ Wnode) {
    __shared__ float xs[DIN];
    __shared__ float ws[DNODE][DIN + 1];
    int n = blockIdx.x;
    int t = threadIdx.x;  // 64
    xs[t] = x[n * DIN + t];
    for (int r = 0; r < DNODE; r++) ws[r][t] = Wnode[r * DIN + t];
    __syncthreads();
    float acc = 0.f;
#pragma unroll
    for (int c = 0; c < DIN; c++) acc += xs[c] * ws[t][c];
    g_h[n * DNODE + t] = acc;
}

// K2: per-edge features.  Writes TMP cols [0,128) and X4/X5.
//     TMP[:,0:32]=SP, [:,32:64]=(SP W2^T)*(SP W3^T), [:,64:128]=diag(h)
__global__ void k_edgefeat(const float* __restrict__ SP, const int* __restrict__ ei,
                           const float* __restrict__ W2, const float* __restrict__ W3,
                           const float* __restrict__ W4, const float* __restrict__ W5) {
    __shared__ float w2[KE][KE + 1], w3[KE][KE + 1], w4[KE][KE + 1], w5[KE][KE + 1];
    __shared__ float sp[8][KE];
    int t = threadIdx.x;  // 256
    for (int i = t; i < KE * KE; i += 256) {
        int r = i / KE, c = i % KE;
        w2[r][c] = W2[i]; w3[r][c] = W3[i]; w4[r][c] = W4[i]; w5[r][c] = W5[i];
    }
    int we = t >> 5, lane = t & 31;
    int e = blockIdx.x * 8 + we;
    sp[we][lane] = SP[e * KE + lane];
    __syncthreads();
    float p2 = 0, p3 = 0, p4 = 0, p5 = 0;
#pragma unroll
    for (int j = 0; j < KE; j++) {
        float s = sp[we][j];
        p2 += s * w2[lane][j];
        p3 += s * w3[lane][j];
        p4 += s * w4[lane][j];
        p5 += s * w5[lane][j];
    }
    g_X4[e * KE + lane] = p4;
    g_X5[e * KE + lane] = p5;
    float* trow = &g_TMP[(size_t)e * TMPW];
    trow[lane] = sp[we][lane];
    trow[32 + lane] = p2 * p3;
    int s_i = ei[e], d_j = ei[N_EDGES + e];
    bool diag = (s_i == d_j);
    trow[64 + lane] = diag ? g_h[s_i * DNODE + lane] : 0.f;
    trow[96 + lane] = diag ? g_h[s_i * DNODE + 32 + lane] : 0.f;
}

// K3: build dense edge-id table + row counts
__global__ void k_build(const int* __restrict__ ei) {
    int e = blockIdx.x * blockDim.x + threadIdx.x;
    if (e < N_EDGES) {
        int s = ei[e], d = ei[N_EDGES + e];
        g_eid[s * N_NODES + d] = e;
        atomicAdd(&g_rowcnt[s], 1);
    }
}

// K4: exclusive scan of row counts (single block, 1024 threads)
__global__ void k_scan() {
    __shared__ int s[N_NODES];
    int t = threadIdx.x;
    s[t] = g_rowcnt[t];
    __syncthreads();
    for (int off = 1; off < N_NODES; off <<= 1) {
        int v = (t >= off) ? s[t - off] : 0;
        __syncthreads();
        s[t] += v;
        __syncthreads();
    }
    g_rowptr[t + 1] = s[t];
    if (t == 0) g_rowptr[0] = 0;
}

// K5: scatter edges into CSR slots
__global__ void k_fill(const int* __restrict__ ei) {
    int e = blockIdx.x * blockDim.x + threadIdx.x;
    if (e < N_EDGES) {
        int s = ei[e];
        int pos = atomicAdd(&g_fill[s], 1);
        g_rowedges[g_rowptr[s] + pos] = e;
    }
}

// K6: sampled sparse-sparse matmul.  One warp per target edge (i,j):
//     TMP[e,128+k] = sum over m: (i,m),(m,j) in E of X4[(i,m),k]*X5[(m,j),k]
__global__ void k_path(const int* __restrict__ ei) {
    int warp = (blockIdx.x * blockDim.x + threadIdx.x) >> 5;
    int lane = threadIdx.x & 31;
    if (warp >= N_EDGES) return;
    int e = warp;
    int i = ei[e], j = ei[N_EDGES + e];
    int start = g_rowptr[i], end = g_rowptr[i + 1];
    float acc = 0.f;
    for (int s = start; s < end; s += 32) {
        int idx = s + lane;
        int e1 = -1, e2 = -1;
        if (idx < end) {
            e1 = g_rowedges[idx];
            int m = ei[N_EDGES + e1];            // dst of (i,m)
            e2 = g_eid[m * N_NODES + j];
        }
        unsigned mask = __ballot_sync(0xFFFFFFFFu, e2 >= 0);
        while (mask) {
            int b = __ffs(mask) - 1;
            mask &= mask - 1;
            int E1 = __shfl_sync(0xFFFFFFFFu, e1, b);
            int E2 = __shfl_sync(0xFFFFFFFFu, e2, b);
            acc += g_X4[E1 * KE + lane] * g_X5[E2 * KE + lane];
        }
    }
    g_TMP[(size_t)e * TMPW + 128 + lane] = acc;
}

// K7: H = relu(TMP @ W6^T)   [E,256], tiled SGEMM (BM=64, BN=64, BK=16)
__global__ void k_gemm1(const float* __restrict__ W6) {
    __shared__ float As[64][16];
    __shared__ float Bs[16][68];
    int t = threadIdx.x;            // 256
    int tx = t & 15, ty = t >> 4;
    int rowBase = blockIdx.y * 64;
    int colBase = blockIdx.x * 64;
    float acc[4][4] = {};
    for (int k0 = 0; k0 < TMPW; k0 += 16) {
        {
            int r = t >> 2, kk = (t & 3) << 2;
            float4 v = *(const float4*)&g_TMP[(size_t)(rowBase + r) * TMPW + k0 + kk];
            *(float4*)&As[r][kk] = v;
        }
        {
            int n = t >> 2, kk = (t & 3) << 2;
            float4 v = *(const float4*)&W6[(colBase + n) * TMPW + k0 + kk];
            Bs[kk][n] = v.x; Bs[kk + 1][n] = v.y; Bs[kk + 2][n] = v.z; Bs[kk + 3][n] = v.w;
        }
        __syncthreads();
#pragma unroll
        for (int kk = 0; kk < 16; kk++) {
            float a[4], b[4];
#pragma unroll
            for (int i = 0; i < 4; i++) a[i] = As[ty * 4 + i][kk];
            float4 bv = *(const float4*)&Bs[kk][tx * 4];
            b[0] = bv.x; b[1] = bv.y; b[2] = bv.z; b[3] = bv.w;
#pragma unroll
            for (int i = 0; i < 4; i++)
#pragma unroll
                for (int j = 0; j < 4; j++) acc[i][j] += a[i] * b[j];
        }
        __syncthreads();
    }
#pragma unroll
    for (int i = 0; i < 4; i++) {
        int r = rowBase + ty * 4 + i;
        float4 v;
        v.x = fmaxf(acc[i][0], 0.f); v.y = fmaxf(acc[i][1], 0.f);
        v.z = fmaxf(acc[i][2], 0.f); v.w = fmaxf(acc[i][3], 0.f);
        *(float4*)&g_H[(size_t)r * HID + colBase + tx * 4] = v;
    }
}

// K8: EA = H @ W7^T   [E,32]  (BM=64, BN=32, BK=32) -> writes into d_out edge region
__global__ void k_gemm2(const float* __restrict__ W7, float* __restrict__ EA) {
    __shared__ float As[64][32];
    __shared__ float Bs[32][33];
    int t = threadIdx.x;            // 256
    int tx = t & 15, ty = t >> 4;   // cols tx*2, rows ty*4
    int rowBase = blockIdx.x * 64;
    float acc[4][2] = {};
    for (int k0 = 0; k0 < HID; k0 += 32) {
#pragma unroll
        for (int l = 0; l < 2; l++) {
            int fid = t + l * 256;
            int r = fid >> 3, kk = (fid & 7) << 2;
            float4 v = *(const float4*)&g_H[(size_t)(rowBase + r) * HID + k0 + kk];
            *(float4*)&As[r][kk] = v;
        }
        {
            int n = t >> 3, kk = (t & 7) << 2;
            float4 v = *(const float4*)&W7[n * HID + k0 + kk];
            Bs[kk][n] = v.x; Bs[kk + 1][n] = v.y; Bs[kk + 2][n] = v.z; Bs[kk + 3][n] = v.w;
        }
        __syncthreads();
#pragma unroll
        for (int kk = 0; kk < 32; kk++) {
            float a[4], b[2];
#pragma unroll
            for (int i = 0; i < 4; i++) a[i] = As[ty * 4 + i][kk];
            b[0] = Bs[kk][tx * 2]; b[1] = Bs[kk][tx * 2 + 1];
#pragma unroll
            for (int i = 0; i < 4; i++) {
                acc[i][0] += a[i] * b[0];
                acc[i][1] += a[i] * b[1];
            }
        }
        __syncthreads();
    }
#pragma unroll
    for (int i = 0; i < 4; i++) {
        int r = rowBase + ty * 4 + i;
        EA[(size_t)r * KOUT + tx * 2] = acc[i][0];
        EA[(size_t)r * KOUT + tx * 2 + 1] = acc[i][1];
    }
}

// K9: per-source outer-product aggregation: AGG[i] = sum_e ea[e] (x) x[dst[e]]
__global__ void k_agg(const float* __restrict__ x, const int* __restrict__ ei,
                      const float* __restrict__ EA) {
    int i = blockIdx.x;
    int t = threadIdx.x;  // 256
    __shared__ float ea_s[KOUT];
    __shared__ float x_s[DIN];
    float acc[8];
#pragma unroll
    for (int q = 0; q < 8; q++) acc[q] = 0.f;
    int start = g_rowptr[i], end = g_rowptr[i + 1];
    for (int p = start; p < end; p++) {
        int e = g_rowedges[p];
        int d = ei[N_EDGES + e];
        __syncthreads();
        if (t < 32) ea_s[t] = EA[(size_t)e * KOUT + t];
        else if (t < 96) x_s[t - 32] = x[d * DIN + (t - 32)];
        __syncthreads();
#pragma unroll
        for (int q = 0; q < 8; q++) {
            int cell = t + q * 256;   // 0..2047 : (k = cell/64, c = cell%64)
            acc[q] += ea_s[cell >> 6] * x_s[cell & 63];
        }
    }
#pragma unroll
    for (int q = 0; q < 8; q++) g_AGG[i * (KOUT * DIN) + t + q * 256] = acc[q];
}

// K10: x_out = AGG[1024,2048] @ conv_w_flat[2048,64] + b   (BM=32, BN=64, BK=32)
__global__ void k_out(const float* __restrict__ CW, const float* __restrict__ CB,
                      float* __restrict__ xout) {
    __shared__ float As[32][32];
    __shared__ float Bs[32][68];
    int t = threadIdx.x;            // 256
    int tx = t & 15, ty = t >> 4;   // rows ty*2, cols tx*4
    int rowBase = blockIdx.x * 32;
    const int KTOT = KOUT * DIN;    // 2048
    float acc[2][4] = {};
    for (int k0 = 0; k0 < KTOT; k0 += 32) {
        {
            int r = t >> 3, kk = (t & 7) << 2;
            float4 v = *(const float4*)&g_AGG[(rowBase + r) * KTOT + k0 + kk];
            *(float4*)&As[r][kk] = v;
        }
#pragma unroll
        for (int l = 0; l < 2; l++) {
            int fid = t + l * 256;
            int kk = fid >> 4, n4 = (fid & 15) << 2;
            float4 v = *(const float4*)&CW[(k0 + kk) * DOUT + n4];
            *(float4*)&Bs[kk][n4] = v;
        }
        __syncthreads();
#pragma unroll
        for (int kk = 0; kk < 32; kk++) {
            float a[2], b[4];
            a[0] = As[ty * 2][kk]; a[1] = As[ty * 2 + 1][kk];
            float4 bv = *(const float4*)&Bs[kk][tx * 4];
            b[0] = bv.x; b[1] = bv.y; b[2] = bv.z; b[3] = bv.w;
#pragma unroll
            for (int i = 0; i < 2; i++)
#pragma unroll
                for (int j = 0; j < 4; j++) acc[i][j] += a[i] * b[j];
        }
        __syncthreads();
    }
#pragma unroll
    for (int i = 0; i < 2; i++) {
        int r = rowBase + ty * 2 + i;
#pragma unroll
        for (int j = 0; j < 4; j++)
            xout[r * DOUT + tx * 4 + j] = acc[i][j] + CB[tx * 4 + j];
    }
}

// ---------------------------------------------------------------
extern "C" void kernel_launch(void* const* d_in, const int* in_sizes, int n_in,
                              void* d_out, int out_size) {
    const float* x     = (const float*)d_in[0];
    const int*   ei    = (const int*)  d_in[1];
    const float* SP    = (const float*)d_in[2];
    // d_in[3] = batch_node (unused)
    const float* Wnode = (const float*)d_in[4];
    const float* W2    = (const float*)d_in[5];
    const float* W3    = (const float*)d_in[6];
    const float* W4    = (const float*)d_in[7];
    const float* W5    = (const float*)d_in[8];
    const float* W6    = (const float*)d_in[9];
    const float* W7    = (const float*)d_in[10];
    const float* CW    = (const float*)d_in[11];
    const float* CB    = (const float*)d_in[12];

    float* xout = (float*)d_out;                       // [1024, 64]
    float* EA   = (float*)d_out + N_NODES * DOUT;      // [32768, 32]

    k_init<<<2048, 512>>>();
    k_h<<<N_NODES, 64>>>(x, Wnode);
    k_edgefeat<<<N_EDGES / 8, 256>>>(SP, ei, W2, W3, W4, W5);
    k_build<<<N_EDGES / 256, 256>>>(ei);
    k_scan<<<1, 1024>>>();
    k_fill<<<N_EDGES / 256, 256>>>(ei);
    k_path<<<N_EDGES / 8, 256>>>(ei);
    k_gemm1<<<dim3(HID / 64, N_EDGES / 64), 256>>>(W6);
    k_gemm2<<<N_EDGES / 64, 256>>>(W7, EA);
    k_agg<<<N_NODES, 256>>>(x, ei, EA);
    k_out<<<N_NODES / 32, 256>>>(CW, CB, xout);
}

// round 5
// speedup vs baseline: 1.1966x; 1.1966x over previous
#include <cuda_runtime.h>
#include <cuda_bf16.h>
#include <mma.h>
#include <cstdint>

using namespace nvcuda;

#define N_NODES 1024
#define N_EDGES 32768
#define KE 32
#define KOUT 32
#define DIN 64
#define DOUT 64
#define DNODE 64
#define KW 160
#define HID 256
#define N_TILES (N_EDGES / 128)   // 256

// -------- device scratch (static; no runtime allocation) --------
__device__ float g_h[N_NODES * DNODE];
__device__ float g_X4[N_EDGES * KE];
__device__ float g_X5[N_EDGES * KE];
__device__ int   g_eid[N_NODES * N_NODES];
__device__ int   g_rowcnt[N_NODES];
__device__ int   g_fill[N_NODES];
__device__ int   g_rowptr[N_NODES + 1];
__device__ int   g_rowedges[N_EDGES];
__device__ float g_AGG[N_NODES * KOUT * DIN];

// bf16 two-term operands (row-major)
__device__ __align__(16) __nv_bfloat16 g_Ahi[(size_t)N_EDGES * KW];
__device__ __align__(16) __nv_bfloat16 g_Alo[(size_t)N_EDGES * KW];
__device__ __align__(16) __nv_bfloat16 g_W6h[HID * KW];
__device__ __align__(16) __nv_bfloat16 g_W6l[HID * KW];
__device__ __align__(16) __nv_bfloat16 g_W7h[KOUT * HID];
__device__ __align__(16) __nv_bfloat16 g_W7l[KOUT * HID];

__device__ __forceinline__ void bf16_split(float v, __nv_bfloat16& h, __nv_bfloat16& l) {
    h = __float2bfloat16(v);
    l = __float2bfloat16(v - __bfloat162float(h));
}

__device__ __forceinline__ void store_a(int e, int col, float v) {
    __nv_bfloat16 h, l;
    bf16_split(v, h, l);
    g_Ahi[(size_t)e * KW + col] = h;
    g_Alo[(size_t)e * KW + col] = l;
}

// ---------------------------------------------------------------
__global__ void k_init() {
    int idx = blockIdx.x * blockDim.x + threadIdx.x;
    int stride = gridDim.x * blockDim.x;
    for (int i = idx; i < N_NODES * N_NODES; i += stride) g_eid[i] = -1;
    if (idx < N_NODES) { g_rowcnt[idx] = 0; g_fill[idx] = 0; }
}

__global__ void k_h(const float* __restrict__ x, const float* __restrict__ Wnode) {
    __shared__ float xs[DIN];
    __shared__ float ws[DNODE][DIN + 1];
    int n = blockIdx.x;
    int t = threadIdx.x;  // 64
    xs[t] = x[n * DIN + t];
    for (int r = 0; r < DNODE; r++) ws[r][t] = Wnode[r * DIN + t];
    __syncthreads();
    float acc = 0.f;
#pragma unroll
    for (int c = 0; c < DIN; c++) acc += xs[c] * ws[t][c];
    g_h[n * DNODE + t] = acc;
}

// convert W6 / W7 to bf16 hi/lo
__global__ void k_wconv(const float* __restrict__ W6, const float* __restrict__ W7) {
    int i = blockIdx.x * blockDim.x + threadIdx.x;
    if (i < HID * KW) {
        __nv_bfloat16 h, l;
        bf16_split(W6[i], h, l);
        g_W6h[i] = h; g_W6l[i] = l;
    } else if (i < HID * KW + KOUT * HID) {
        int j = i - HID * KW;
        __nv_bfloat16 h, l;
        bf16_split(W7[j], h, l);
        g_W7h[j] = h; g_W7l[j] = l;
    }
}

// per-edge features -> A cols [0,128); also X4/X5
__global__ void k_edgefeat(const float* __restrict__ SP, const int* __restrict__ ei,
                           const float* __restrict__ W2, const float* __restrict__ W3,
                           const float* __restrict__ W4, const float* __restrict__ W5) {
    __shared__ float w2[KE][KE + 1], w3[KE][KE + 1], w4[KE][KE + 1], w5[KE][KE + 1];
    __shared__ float sp[8][KE];
    int t = threadIdx.x;  // 256
    for (int i = t; i < KE * KE; i += 256) {
        int r = i / KE, c = i % KE;
        w2[r][c] = W2[i]; w3[r][c] = W3[i]; w4[r][c] = W4[i]; w5[r][c] = W5[i];
    }
    int we = t >> 5, lane = t & 31;
    int e = blockIdx.x * 8 + we;
    sp[we][lane] = SP[e * KE + lane];
    __syncthreads();
    float p2 = 0, p3 = 0, p4 = 0, p5 = 0;
#pragma unroll
    for (int j = 0; j < KE; j++) {
        float s = sp[we][j];
        p2 += s * w2[lane][j];
        p3 += s * w3[lane][j];
        p4 += s * w4[lane][j];
        p5 += s * w5[lane][j];
    }
    g_X4[e * KE + lane] = p4;
    g_X5[e * KE + lane] = p5;
    int s_i = ei[e], d_j = ei[N_EDGES + e];
    bool diag = (s_i == d_j);
    store_a(e, lane, sp[we][lane]);
    store_a(e, 32 + lane, p2 * p3);
    store_a(e, 64 + lane, diag ? g_h[s_i * DNODE + lane] : 0.f);
    store_a(e, 96 + lane, diag ? g_h[s_i * DNODE + 32 + lane] : 0.f);
}

__global__ void k_build(const int* __restrict__ ei) {
    int e = blockIdx.x * blockDim.x + threadIdx.x;
    if (e < N_EDGES) {
        int s = ei[e], d = ei[N_EDGES + e];
        g_eid[s * N_NODES + d] = e;
        atomicAdd(&g_rowcnt[s], 1);
    }
}

__global__ void k_scan() {
    __shared__ int s[N_NODES];
    int t = threadIdx.x;
    s[t] = g_rowcnt[t];
    __syncthreads();
    for (int off = 1; off < N_NODES; off <<= 1) {
        int v = (t >= off) ? s[t - off] : 0;
        __syncthreads();
        s[t] += v;
        __syncthreads();
    }
    g_rowptr[t + 1] = s[t];
    if (t == 0) g_rowptr[0] = 0;
}

__global__ void k_fill(const int* __restrict__ ei) {
    int e = blockIdx.x * blockDim.x + threadIdx.x;
    if (e < N_EDGES) {
        int s = ei[e];
        int pos = atomicAdd(&g_fill[s], 1);
        g_rowedges[g_rowptr[s] + pos] = e;
    }
}

// sampled sparse-sparse matmul -> A cols [128,160)
__global__ void k_path(const int* __restrict__ ei) {
    int warp = (blockIdx.x * blockDim.x + threadIdx.x) >> 5;
    int lane = threadIdx.x & 31;
    if (warp >= N_EDGES) return;
    int e = warp;
    int i = ei[e], j = ei[N_EDGES + e];
    int start = g_rowptr[i], end = g_rowptr[i + 1];
    float acc = 0.f;
    for (int s = start; s < end; s += 32) {
        int idx = s + lane;
        int e1 = -1, e2 = -1;
        if (idx < end) {
            e1 = g_rowedges[idx];
            int m = ei[N_EDGES + e1];
            e2 = g_eid[m * N_NODES + j];
        }
        unsigned mask = __ballot_sync(0xFFFFFFFFu, e2 >= 0);
        while (mask) {
            int b = __ffs(mask) - 1;
            mask &= mask - 1;
            int E1 = __shfl_sync(0xFFFFFFFFu, e1, b);
            int E2 = __shfl_sync(0xFFFFFFFFu, e2, b);
            acc += g_X4[E1 * KE + lane] * g_X5[E2 * KE + lane];
        }
    }
    store_a(e, 128 + lane, acc);
}

// ---------------- fused WMMA edge MLP: EA = relu(TMP@W6^T)@W7^T ----------------
// smem byte offsets
#define AS_LD   168
#define W6S_LD  168
#define W7S_LD  264
#define HS_LD   72
#define OFF_AH  0
#define OFF_AL  (OFF_AH + 128 * AS_LD * 2)        // 43008
#define OFF_W6H (OFF_AL + 128 * AS_LD * 2)        // 86016
#define OFF_W6L (OFF_W6H + 64 * W6S_LD * 2)       // 107520
#define OFF_W7H (OFF_W6L + 64 * W6S_LD * 2)       // 129024
#define OFF_W7L (OFF_W7H + 32 * W7S_LD * 2)       // 145920
#define OFF_HH  (OFF_W7L + 32 * W7S_LD * 2)       // 162816
#define OFF_HL  (OFF_HH + 128 * HS_LD * 2)        // 181248
#define SMEM_FUSED (OFF_HL + 128 * HS_LD * 2)     // 199680
#define OFF_CBUF OFF_W6H                          // fp32 128x68 (34816B) reuses W6 region
#define CB_LD   68
#define EB_LD   36

__global__ __launch_bounds__(256, 1) void k_fused(float* __restrict__ EA) {
    extern __shared__ char S[];
    int t = threadIdx.x;
    int w = t >> 5, lane = t & 31;
    int tile = blockIdx.x;

    __nv_bfloat16* sAh  = (__nv_bfloat16*)(S + OFF_AH);
    __nv_bfloat16* sAl  = (__nv_bfloat16*)(S + OFF_AL);
    __nv_bfloat16* sW6h = (__nv_bfloat16*)(S + OFF_W6H);
    __nv_bfloat16* sW6l = (__nv_bfloat16*)(S + OFF_W6L);
    __nv_bfloat16* sW7h = (__nv_bfloat16*)(S + OFF_W7H);
    __nv_bfloat16* sW7l = (__nv_bfloat16*)(S + OFF_W7L);
    __nv_bfloat16* sHh  = (__nv_bfloat16*)(S + OFF_HH);
    __nv_bfloat16* sHl  = (__nv_bfloat16*)(S + OFF_HL);
    float* Cbuf = (float*)(S + OFF_CBUF);

    // load A tile (hi/lo) and full W7 (hi/lo)
    {
        const uint4* aH = (const uint4*)(g_Ahi + (size_t)tile * 128 * KW);
        const uint4* aL = (const uint4*)(g_Alo + (size_t)tile * 128 * KW);
        for (int i = t; i < 128 * 20; i += 256) {        // 20 uint4 per 160-el row
            int r = i / 20, sgi = i % 20;
            *(uint4*)&sAh[r * AS_LD + sgi * 8] = aH[i];
            *(uint4*)&sAl[r * AS_LD + sgi * 8] = aL[i];
        }
        const uint4* wH = (const uint4*)g_W7h;
        const uint4* wL = (const uint4*)g_W7l;
        for (int i = t; i < 32 * 32; i += 256) {         // 32 uint4 per 256-el row
            int r = i / 32, sgi = i % 32;
            *(uint4*)&sW7h[r * W7S_LD + sgi * 8] = wH[i];
            *(uint4*)&sW7l[r * W7S_LD + sgi * 8] = wL[i];
        }
    }

    wmma::fragment<wmma::accumulator, 16, 16, 16, float> ea[2];
    wmma::fill_fragment(ea[0], 0.f);
    wmma::fill_fragment(ea[1], 0.f);

    for (int nc = 0; nc < 4; nc++) {
        __syncthreads();   // A/W7 ready (nc=0); Cbuf consumed (nc>0)
        // load W6 chunk rows [nc*64, nc*64+64)
        {
            const uint4* bH = (const uint4*)(g_W6h + (size_t)nc * 64 * KW);
            const uint4* bL = (const uint4*)(g_W6l + (size_t)nc * 64 * KW);
            for (int i = t; i < 64 * 20; i += 256) {
                int r = i / 20, sgi = i % 20;
                *(uint4*)&sW6h[r * W6S_LD + sgi * 8] = bH[i];
                *(uint4*)&sW6l[r * W6S_LD + sgi * 8] = bL[i];
            }
        }
        __syncthreads();

        // GEMM1 chunk: C[128,64] = A[128,160] @ W6c^T, warp w -> rows [w*16, w*16+16)
        wmma::fragment<wmma::accumulator, 16, 16, 16, float> c[4];
#pragma unroll
        for (int n = 0; n < 4; n++) wmma::fill_fragment(c[n], 0.f);
#pragma unroll
        for (int k = 0; k < 10; k++) {
            wmma::fragment<wmma::matrix_a, 16, 16, 16, __nv_bfloat16, wmma::row_major> ah, al;
            wmma::load_matrix_sync(ah, sAh + w * 16 * AS_LD + k * 16, AS_LD);
            wmma::load_matrix_sync(al, sAl + w * 16 * AS_LD + k * 16, AS_LD);
#pragma unroll
            for (int n = 0; n < 4; n++) {
                wmma::fragment<wmma::matrix_b, 16, 16, 16, __nv_bfloat16, wmma::col_major> bh, bl;
                wmma::load_matrix_sync(bh, sW6h + n * 16 * W6S_LD + k * 16, W6S_LD);
                wmma::load_matrix_sync(bl, sW6l + n * 16 * W6S_LD + k * 16, W6S_LD);
                wmma::mma_sync(c[n], ah, bh, c[n]);
                wmma::mma_sync(c[n], ah, bl, c[n]);
                wmma::mma_sync(c[n], al, bh, c[n]);
            }
        }
        __syncthreads();   // all warps done reading W6 chunk; Cbuf region free

        // store fp32 C, relu + split to bf16 hi/lo H chunk (warp-local rows)
#pragma unroll
        for (int n = 0; n < 4; n++)
            wmma::store_matrix_sync(Cbuf + w * 16 * CB_LD + n * 16, c[n], CB_LD, wmma::mem_row_major);
        __syncwarp();
#pragma unroll
        for (int idx = 0; idx < 32; idx++) {
            int f = lane + idx * 32;           // 0..1023
            int r = f >> 6, cc = f & 63;
            float v = fmaxf(Cbuf[(w * 16 + r) * CB_LD + cc], 0.f);
            __nv_bfloat16 h, l;
            bf16_split(v, h, l);
            sHh[(w * 16 + r) * HS_LD + cc] = h;
            sHl[(w * 16 + r) * HS_LD + cc] = l;
        }
        __syncwarp();

        // GEMM2 partial: EA[w rows] += Hc[16,64] @ W7c^T  (K cols nc*64..nc*64+64)
#pragma unroll
        for (int k2 = 0; k2 < 4; k2++) {
            wmma::fragment<wmma::matrix_a, 16, 16, 16, __nv_bfloat16, wmma::row_major> ah, al;
            wmma::load_matrix_sync(ah, sHh + w * 16 * HS_LD + k2 * 16, HS_LD);
            wmma::load_matrix_sync(al, sHl + w * 16 * HS_LD + k2 * 16, HS_LD);
#pragma unroll
            for (int n = 0; n < 2; n++) {
                wmma::fragment<wmma::matrix_b, 16, 16, 16, __nv_bfloat16, wmma::col_major> bh, bl;
                wmma::load_matrix_sync(bh, sW7h + n * 16 * W7S_LD + nc * 64 + k2 * 16, W7S_LD);
                wmma::load_matrix_sync(bl, sW7l + n * 16 * W7S_LD + nc * 64 + k2 * 16, W7S_LD);
                wmma::mma_sync(ea[n], ah, bh, ea[n]);
                wmma::mma_sync(ea[n], ah, bl, ea[n]);
                wmma::mma_sync(ea[n], al, bh, ea[n]);
            }
        }
    }

    // epilogue: EA frags -> smem -> coalesced global store
    __syncthreads();
    float* Ebuf = Cbuf;                        // 128 x 36 fp32
    wmma::store_matrix_sync(Ebuf + w * 16 * EB_LD, ea[0], EB_LD, wmma::mem_row_major);
    wmma::store_matrix_sync(Ebuf + w * 16 * EB_LD + 16, ea[1], EB_LD, wmma::mem_row_major);
    __syncthreads();
    for (int f = t; f < 1024; f += 256) {      // 128 rows x 8 float4
        int r = f >> 3, sgi = f & 7;
        float4 v = *(float4*)&Ebuf[r * EB_LD + sgi * 4];
        *(float4*)&EA[((size_t)tile * 128 + r) * KOUT + sgi * 4] = v;
    }
}

// ---------------- aggregation + output ----------------
__global__ void k_agg(const float* __restrict__ x, const int* __restrict__ ei,
                      const float* __restrict__ EA) {
    int i = blockIdx.x;
    int t = threadIdx.x;  // 256
    __shared__ float ea_s[KOUT];
    __shared__ float x_s[DIN];
    float acc[8];
#pragma unroll
    for (int q = 0; q < 8; q++) acc[q] = 0.f;
    int start = g_rowptr[i], end = g_rowptr[i + 1];
    for (int p = start; p < end; p++) {
        int e = g_rowedges[p];
        int d = ei[N_EDGES + e];
        __syncthreads();
        if (t < 32) ea_s[t] = EA[(size_t)e * KOUT + t];
        else if (t < 96) x_s[t - 32] = x[d * DIN + (t - 32)];
        __syncthreads();
#pragma unroll
        for (int q = 0; q < 8; q++) {
            int cell = t + q * 256;
            acc[q] += ea_s[cell >> 6] * x_s[cell & 63];
        }
    }
#pragma unroll
    for (int q = 0; q < 8; q++) g_AGG[i * (KOUT * DIN) + t + q * 256] = acc[q];
}

__global__ void k_out(const float* __restrict__ CW, const float* __restrict__ CB,
                      float* __restrict__ xout) {
    __shared__ float As[32][32];
    __shared__ float Bs[32][68];
    int t = threadIdx.x;            // 256
    int tx = t & 15, ty = t >> 4;
    int rowBase = blockIdx.x * 32;
    const int KTOT = KOUT * DIN;    // 2048
    float acc[2][4] = {};
    for (int k0 = 0; k0 < KTOT; k0 += 32) {
        {
            int r = t >> 3, kk = (t & 7) << 2;
            float4 v = *(const float4*)&g_AGG[(rowBase + r) * KTOT + k0 + kk];
            *(float4*)&As[r][kk] = v;
        }
#pragma unroll
        for (int l = 0; l < 2; l++) {
            int fid = t + l * 256;
            int kk = fid >> 4, n4 = (fid & 15) << 2;
            float4 v = *(const float4*)&CW[(k0 + kk) * DOUT + n4];
            *(float4*)&Bs[kk][n4] = v;
        }
        __syncthreads();
#pragma unroll
        for (int kk = 0; kk < 32; kk++) {
            float a[2], b[4];
            a[0] = As[ty * 2][kk]; a[1] = As[ty * 2 + 1][kk];
            float4 bv = *(const float4*)&Bs[kk][tx * 4];
            b[0] = bv.x; b[1] = bv.y; b[2] = bv.z; b[3] = bv.w;
#pragma unroll
            for (int i = 0; i < 2; i++)
#pragma unroll
                for (int j = 0; j < 4; j++) acc[i][j] += a[i] * b[j];
        }
        __syncthreads();
    }
#pragma unroll
    for (int i = 0; i < 2; i++) {
        int r = rowBase + ty * 2 + i;
#pragma unroll
        for (int j = 0; j < 4; j++)
            xout[r * DOUT + tx * 4 + j] = acc[i][j] + CB[tx * 4 + j];
    }
}

// ---------------------------------------------------------------
extern "C" void kernel_launch(void* const* d_in, const int* in_sizes, int n_in,
                              void* d_out, int out_size) {
    const float* x     = (const float*)d_in[0];
    const int*   ei    = (const int*)  d_in[1];
    const float* SP    = (const float*)d_in[2];
    const float* Wnode = (const float*)d_in[4];
    const float* W2    = (const float*)d_in[5];
    const float* W3    = (const float*)d_in[6];
    const float* W4    = (const float*)d_in[7];
    const float* W5    = (const float*)d_in[8];
    const float* W6    = (const float*)d_in[9];
    const float* W7    = (const float*)d_in[10];
    const float* CW    = (const float*)d_in[11];
    const float* CB    = (const float*)d_in[12];

    float* xout = (float*)d_out;                       // [1024, 64]
    float* EA   = (float*)d_out + N_NODES * DOUT;      // [32768, 32]

    // no static guard (harness rule): idempotent, cheap, capture-safe
    cudaFuncSetAttribute(k_fused, cudaFuncAttributeMaxDynamicSharedMemorySize, SMEM_FUSED);

    k_init<<<2048, 512>>>();
    k_h<<<N_NODES, 64>>>(x, Wnode);
    k_wconv<<<(HID * KW + KOUT * HID + 255) / 256, 256>>>(W6, W7);
    k_edgefeat<<<N_EDGES / 8, 256>>>(SP, ei, W2, W3, W4, W5);
    k_build<<<N_EDGES / 256, 256>>>(ei);
    k_scan<<<1, 1024>>>();
    k_fill<<<N_EDGES / 256, 256>>>(ei);
    k_path<<<N_EDGES / 8, 256>>>(ei);
    k_fused<<<N_TILES, 256, SMEM_FUSED>>>(EA);
    k_agg<<<N_NODES, 256>>>(x, ei, EA);
    k_out<<<N_NODES / 32, 256>>>(CW, CB, xout);
}